// round 2
// baseline (speedup 1.0000x reference)
#include <cuda_runtime.h>
#include <math.h>

#define Dm   768
#define Hh   12
#define HDm  64
#define DFFm 3072
#define Bb   2
#define Ss   4096
#define NT   (Bb*Ss)   // 8192 token rows
#define AST  68        // attention shared-tile row stride (multiple of 4!)

// ---- scratch (device globals; no allocation allowed) ----
__device__ float g_h  [NT*Dm];
__device__ float g_q  [NT*Dm];
__device__ float g_k  [NT*Dm];
__device__ float g_v  [NT*Dm];
__device__ float g_ctx[NT*Dm];
__device__ float g_x1 [NT*Dm];
__device__ float g_h2 [NT*Dm];
__device__ float g_ff1[NT*DFFm];

// ============================ LayerNorm ============================
// one block (256 threads) per row of 768
__global__ void ln_kernel(const float* __restrict__ x,
                          const float* __restrict__ g,
                          const float* __restrict__ b,
                          float* __restrict__ out) {
    int row = blockIdx.x;
    const float* xr = x + (size_t)row * Dm;
    int tid = threadIdx.x;
    float v0 = xr[tid], v1 = xr[tid + 256], v2 = xr[tid + 512];
    float s  = v0 + v1 + v2;
    float s2 = v0*v0 + v1*v1 + v2*v2;
    #pragma unroll
    for (int o = 16; o; o >>= 1) {
        s  += __shfl_xor_sync(0xffffffffu, s,  o);
        s2 += __shfl_xor_sync(0xffffffffu, s2, o);
    }
    __shared__ float ws[8], ws2[8];
    int w = tid >> 5, l = tid & 31;
    if (l == 0) { ws[w] = s; ws2[w] = s2; }
    __syncthreads();
    __shared__ float smu, srs;
    if (w == 0) {
        s  = (l < 8) ? ws[l]  : 0.f;
        s2 = (l < 8) ? ws2[l] : 0.f;
        #pragma unroll
        for (int o = 4; o; o >>= 1) {
            s  += __shfl_xor_sync(0xffffffffu, s,  o);
            s2 += __shfl_xor_sync(0xffffffffu, s2, o);
        }
        if (l == 0) {
            float mu  = s / Dm;
            float var = fmaxf(s2 / Dm - mu * mu, 0.f);
            smu = mu;
            srs = rsqrtf(var + 1e-5f);
        }
    }
    __syncthreads();
    float mu = smu, rs = srs;
    float* outr = out + (size_t)row * Dm;
    outr[tid]       = (v0 - mu) * rs * g[tid]       + b[tid];
    outr[tid + 256] = (v1 - mu) * rs * g[tid + 256] + b[tid + 256];
    outr[tid + 512] = (v2 - mu) * rs * g[tid + 512] + b[tid + 512];
}

// ============================ SGEMM ============================
// C[M,N] = A[M,K] @ B[K,N] + bias (+ optional residual, optional relu)
// 128x128x8 tiles, 256 threads, 8x8 per thread. All dims divide evenly.
template<bool RELU, bool RES>
__global__ void sgemm_kernel(const float* __restrict__ A,
                             const float* __restrict__ B,
                             const float* __restrict__ bias,
                             const float* __restrict__ res,
                             float* __restrict__ C,
                             int M, int N, int K) {
    __shared__ float As[8][128];
    __shared__ float Bs[8][128];
    int tid = threadIdx.x;
    int tx = tid & 15, ty = tid >> 4;
    int row0 = blockIdx.y * 128, col0 = blockIdx.x * 128;

    int a_row = tid >> 1, a_col = (tid & 1) * 4;
    int b_row = tid >> 5, b_col = (tid & 31) * 4;
    const float* Ap = A + (size_t)(row0 + a_row) * K + a_col;
    const float* Bp = B + (size_t)b_row * N + col0 + b_col;

    float acc[8][8];
    #pragma unroll
    for (int i = 0; i < 8; i++)
        #pragma unroll
        for (int j = 0; j < 8; j++) acc[i][j] = 0.f;

    for (int k0 = 0; k0 < K; k0 += 8) {
        float4 av = *(const float4*)(Ap + k0);
        As[a_col + 0][a_row] = av.x;
        As[a_col + 1][a_row] = av.y;
        As[a_col + 2][a_row] = av.z;
        As[a_col + 3][a_row] = av.w;
        float4 bv = *(const float4*)(Bp + (size_t)k0 * N);
        *(float4*)&Bs[b_row][b_col] = bv;
        __syncthreads();
        #pragma unroll
        for (int kk = 0; kk < 8; kk++) {
            float ar[8], br[8];
            *(float4*)&ar[0] = *(const float4*)&As[kk][ty * 8];
            *(float4*)&ar[4] = *(const float4*)&As[kk][ty * 8 + 4];
            *(float4*)&br[0] = *(const float4*)&Bs[kk][tx * 8];
            *(float4*)&br[4] = *(const float4*)&Bs[kk][tx * 8 + 4];
            #pragma unroll
            for (int i = 0; i < 8; i++)
                #pragma unroll
                for (int j = 0; j < 8; j++)
                    acc[i][j] = fmaf(ar[i], br[j], acc[i][j]);
        }
        __syncthreads();
    }

    #pragma unroll
    for (int i = 0; i < 8; i++) {
        int r = row0 + ty * 8 + i;
        #pragma unroll
        for (int j = 0; j < 8; j += 4) {
            int c = col0 + tx * 8 + j;
            float4 bv = *(const float4*)&bias[c];
            float4 o;
            o.x = acc[i][j + 0] + bv.x;
            o.y = acc[i][j + 1] + bv.y;
            o.z = acc[i][j + 2] + bv.z;
            o.w = acc[i][j + 3] + bv.w;
            if (RELU) {
                o.x = fmaxf(o.x, 0.f); o.y = fmaxf(o.y, 0.f);
                o.z = fmaxf(o.z, 0.f); o.w = fmaxf(o.w, 0.f);
            }
            if (RES) {
                float4 rv = *(const float4*)&res[(size_t)r * N + c];
                o.x += rv.x; o.y += rv.y; o.z += rv.z; o.w += rv.w;
            }
            *(float4*)&C[(size_t)r * N + c] = o;
        }
    }
}

// ============================ Flash attention (fp32) ============================
// grid: (S/64, H, B), 256 threads.
// Thread t: query row r = t/4, lane-subgroup c0 = t%4.
//   score columns owned: j = c0 + 4*jj (interleaved -> conflict-free Ks reads)
//   output head-dims owned: cg = c0*16 .. +15 (contiguous -> coalesced stores)
__global__ void attn_kernel(const float* __restrict__ Q,
                            const float* __restrict__ Kp,
                            const float* __restrict__ V,
                            const int*   __restrict__ am,
                            float* __restrict__ O) {
    extern __shared__ float sm[];
    float* Qs = sm;                // [64][AST]
    float* Ks = Qs + 64 * AST;     // [64][AST]
    float* Vs = Ks + 64 * AST;     // [64][AST]
    float* Ps = Vs + 64 * AST;     // [64][AST]

    int tid = threadIdx.x;
    int q0 = blockIdx.x * 64;
    int h  = blockIdx.y;
    int b  = blockIdx.z;
    int r  = tid >> 2;            // query row within tile
    int c0 = tid & 3;
    int cg = c0 * 16;             // owned output head-dim slice

    // load Q tile
    {
        const float* src = Q + ((size_t)(b * Ss + q0 + r)) * Dm + h * HDm + cg;
        float* dst = Qs + r * AST + cg;
        #pragma unroll
        for (int i = 0; i < 16; i += 4) *(float4*)(dst + i) = *(const float4*)(src + i);
    }

    float acc[16];
    #pragma unroll
    for (int i = 0; i < 16; i++) acc[i] = 0.f;
    float m = -INFINITY, l = 0.f;
    int qg = q0 + r;

    int ktiles = blockIdx.x + 1;  // causal: keys up to q0+63
    for (int kt = 0; kt < ktiles; kt++) {
        int k0 = kt * 64;
        {
            const float* ks = Kp + ((size_t)(b * Ss + k0 + r)) * Dm + h * HDm + cg;
            const float* vs = V  + ((size_t)(b * Ss + k0 + r)) * Dm + h * HDm + cg;
            float* kd = Ks + r * AST + cg;
            float* vd = Vs + r * AST + cg;
            #pragma unroll
            for (int i = 0; i < 16; i += 4) {
                *(float4*)(kd + i) = *(const float4*)(ks + i);
                *(float4*)(vd + i) = *(const float4*)(vs + i);
            }
        }
        __syncthreads();

        // scores for owned 16 interleaved columns j = c0 + 4*jj
        float s[16];
        #pragma unroll
        for (int jj = 0; jj < 16; jj++) {
            int j = c0 + 4 * jj;
            float a = 0.f;
            #pragma unroll
            for (int kk = 0; kk < 64; kk++)
                a = fmaf(Qs[r * AST + kk], Ks[j * AST + kk], a);
            int kg = k0 + j;
            bool keep = (kg <= qg) && (am[b * Ss + kg] != 0);
            s[jj] = keep ? a * 0.125f : -INFINITY;
        }

        float tmax = s[0];
        #pragma unroll
        for (int jj = 1; jj < 16; jj++) tmax = fmaxf(tmax, s[jj]);
        tmax = fmaxf(tmax, __shfl_xor_sync(0xffffffffu, tmax, 1));
        tmax = fmaxf(tmax, __shfl_xor_sync(0xffffffffu, tmax, 2));

        float m_new = fmaxf(m, tmax);
        float alpha = (m_new == -INFINITY) ? 1.f : expf(m - m_new);

        float psum = 0.f;
        #pragma unroll
        for (int jj = 0; jj < 16; jj++) {
            float p = (m_new == -INFINITY) ? 0.f : expf(s[jj] - m_new);
            Ps[r * AST + c0 + 4 * jj] = p;
            psum += p;
        }
        psum += __shfl_xor_sync(0xffffffffu, psum, 1);
        psum += __shfl_xor_sync(0xffffffffu, psum, 2);
        l = l * alpha + psum;
        m = m_new;
        #pragma unroll
        for (int i = 0; i < 16; i++) acc[i] *= alpha;
        __syncwarp();   // Ps row written by the 4 lanes of this warp sharing r

        // acc += P @ V for owned head-dims
        for (int j = 0; j < 64; j++) {
            float p = Ps[r * AST + j];
            #pragma unroll
            for (int i = 0; i < 16; i++)
                acc[i] = fmaf(p, Vs[j * AST + cg + i], acc[i]);
        }
        __syncthreads();
    }

    float rl = (l > 0.f) ? 1.f / l : 0.f;
    float* op = O + ((size_t)(b * Ss + q0 + r)) * Dm + h * HDm + cg;
    #pragma unroll
    for (int i = 0; i < 16; i++) op[i] = acc[i] * rl;
}

// ============================ launch ============================
extern "C" void kernel_launch(void* const* d_in, const int* in_sizes, int n_in,
                              void* d_out, int out_size) {
    const float* x     = (const float*)d_in[0];
    const int*   am    = (const int*)  d_in[1];
    const float* ln1_g = (const float*)d_in[2];
    const float* ln1_b = (const float*)d_in[3];
    const float* ln2_g = (const float*)d_in[4];
    const float* ln2_b = (const float*)d_in[5];
    const float* Wq = (const float*)d_in[6];
    const float* bq = (const float*)d_in[7];
    const float* Wk = (const float*)d_in[8];
    const float* bk = (const float*)d_in[9];
    const float* Wv = (const float*)d_in[10];
    const float* bv = (const float*)d_in[11];
    const float* Wo = (const float*)d_in[12];
    const float* bo = (const float*)d_in[13];
    const float* W1 = (const float*)d_in[14];
    const float* b1 = (const float*)d_in[15];
    const float* W2 = (const float*)d_in[16];
    const float* b2 = (const float*)d_in[17];
    float* out = (float*)d_out;

    float *h, *q, *k, *v, *ctx, *x1, *h2, *ff1;
    cudaGetSymbolAddress((void**)&h,   g_h);
    cudaGetSymbolAddress((void**)&q,   g_q);
    cudaGetSymbolAddress((void**)&k,   g_k);
    cudaGetSymbolAddress((void**)&v,   g_v);
    cudaGetSymbolAddress((void**)&ctx, g_ctx);
    cudaGetSymbolAddress((void**)&x1,  g_x1);
    cudaGetSymbolAddress((void**)&h2,  g_h2);
    cudaGetSymbolAddress((void**)&ff1, g_ff1);

    // LN1
    ln_kernel<<<NT, 256>>>(x, ln1_g, ln1_b, h);

    // QKV projections
    dim3 gD(Dm / 128, NT / 128);
    sgemm_kernel<false, false><<<gD, 256>>>(h, Wq, bq, nullptr, q, NT, Dm, Dm);
    sgemm_kernel<false, false><<<gD, 256>>>(h, Wk, bk, nullptr, k, NT, Dm, Dm);
    sgemm_kernel<false, false><<<gD, 256>>>(h, Wv, bv, nullptr, v, NT, Dm, Dm);

    // attention
    const int ATTN_SMEM = 4 * 64 * AST * 4;
    cudaFuncSetAttribute(attn_kernel, cudaFuncAttributeMaxDynamicSharedMemorySize, ATTN_SMEM);
    attn_kernel<<<dim3(Ss / 64, Hh, Bb), 256, ATTN_SMEM>>>(q, k, v, am, ctx);

    // output projection + residual(x)
    sgemm_kernel<false, true><<<gD, 256>>>(ctx, Wo, bo, x, x1, NT, Dm, Dm);

    // LN2
    ln_kernel<<<NT, 256>>>(x1, ln2_g, ln2_b, h2);

    // FFN
    sgemm_kernel<true, false><<<dim3(DFFm / 128, NT / 128), 256>>>(h2, W1, b1, nullptr, ff1, NT, DFFm, Dm);
    sgemm_kernel<false, true><<<gD, 256>>>(ff1, W2, b2, x1, out, NT, Dm, DFFm);
}

// round 3
// speedup vs baseline: 1.3277x; 1.3277x over previous
#include <cuda_runtime.h>
#include <math.h>
#include <stdint.h>

#define Dm   768
#define Hh   12
#define HDm  64
#define DFFm 3072
#define Bb   2
#define Ss   4096
#define NT   (Bb*Ss)   // 8192 token rows
#define AST  68        // attention shared-tile row stride (multiple of 4)

// ---- scratch (device globals; no allocation allowed) ----
__device__ float g_h  [NT*Dm];
__device__ float g_q  [NT*Dm];
__device__ float g_k  [NT*Dm];
__device__ float g_v  [NT*Dm];
__device__ float g_ctx[NT*Dm];
__device__ float g_x1 [NT*Dm];
__device__ float g_h2 [NT*Dm];
__device__ float g_ff1[NT*DFFm];

// ---------- helpers ----------
__device__ __forceinline__ uint32_t f2tf32(float f) {
    uint32_t r;
    asm("cvt.rna.tf32.f32 %0, %1;" : "=r"(r) : "f"(f));
    return r;
}

__device__ __forceinline__ float2 fma2(float2 a, float2 b, float2 c) {
    float2 d;
    asm("fma.rn.f32x2 %0, %1, %2, %3;"
        : "=l"(reinterpret_cast<unsigned long long&>(d))
        : "l"(reinterpret_cast<unsigned long long&>(a)),
          "l"(reinterpret_cast<unsigned long long&>(b)),
          "l"(reinterpret_cast<unsigned long long&>(c)));
    return d;
}

// ============================ LayerNorm ============================
__global__ void ln_kernel(const float* __restrict__ x,
                          const float* __restrict__ g,
                          const float* __restrict__ b,
                          float* __restrict__ out) {
    int row = blockIdx.x;
    const float* xr = x + (size_t)row * Dm;
    int tid = threadIdx.x;
    float v0 = xr[tid], v1 = xr[tid + 256], v2 = xr[tid + 512];
    float s  = v0 + v1 + v2;
    float s2 = v0*v0 + v1*v1 + v2*v2;
    #pragma unroll
    for (int o = 16; o; o >>= 1) {
        s  += __shfl_xor_sync(0xffffffffu, s,  o);
        s2 += __shfl_xor_sync(0xffffffffu, s2, o);
    }
    __shared__ float ws[8], ws2[8];
    int w = tid >> 5, l = tid & 31;
    if (l == 0) { ws[w] = s; ws2[w] = s2; }
    __syncthreads();
    __shared__ float smu, srs;
    if (w == 0) {
        s  = (l < 8) ? ws[l]  : 0.f;
        s2 = (l < 8) ? ws2[l] : 0.f;
        #pragma unroll
        for (int o = 4; o; o >>= 1) {
            s  += __shfl_xor_sync(0xffffffffu, s,  o);
            s2 += __shfl_xor_sync(0xffffffffu, s2, o);
        }
        if (l == 0) {
            float mu  = s / Dm;
            float var = fmaxf(s2 / Dm - mu * mu, 0.f);
            smu = mu;
            srs = rsqrtf(var + 1e-5f);
        }
    }
    __syncthreads();
    float mu = smu, rs = srs;
    float* outr = out + (size_t)row * Dm;
    outr[tid]       = (v0 - mu) * rs * g[tid]       + b[tid];
    outr[tid + 256] = (v1 - mu) * rs * g[tid + 256] + b[tid + 256];
    outr[tid + 512] = (v2 - mu) * rs * g[tid + 512] + b[tid + 512];
}

// ============================ TF32 tensor-core GEMM ============================
// C[M,N] = A[M,K] @ B[K,N] + bias (+res, +relu). 128x128x32 CTA tile,
// 256 threads = 8 warps in 2(M)x4(N); warp tile 64x32 via mma.m16n8k8 tf32.
#define ASTR 36    // As row stride (words): conflict-free frag loads
#define BSTR 136   // Bs row stride (words): conflict-free frag loads

template<bool RELU, bool RES>
__global__ void tf32gemm_kernel(const float* __restrict__ A,
                                const float* __restrict__ B,
                                const float* __restrict__ bias,
                                const float* __restrict__ res,
                                float* __restrict__ C,
                                int M, int N, int K) {
    __shared__ uint32_t As[128 * ASTR];
    __shared__ uint32_t Bs[32 * BSTR];

    int tid  = threadIdx.x;
    int lane = tid & 31;
    int warp = tid >> 5;
    int warp_m = warp & 1;        // 0..1
    int warp_n = warp >> 1;       // 0..3
    int grp = lane >> 2;          // 0..7
    int thr = lane & 3;           // 0..3

    int row0 = blockIdx.y * 128;
    int col0 = blockIdx.x * 128;

    float c[4][4][4];
    #pragma unroll
    for (int mt = 0; mt < 4; mt++)
        #pragma unroll
        for (int nt = 0; nt < 4; nt++)
            #pragma unroll
            for (int i = 0; i < 4; i++) c[mt][nt][i] = 0.f;

    for (int k0 = 0; k0 < K; k0 += 32) {
        // load A tile 128x32 (4 float4 per thread)
        #pragma unroll
        for (int it = 0; it < 4; it++) {
            int i = it * 256 + tid;
            int r = i >> 3;
            int kc = (i & 7) * 4;
            float4 v = *(const float4*)(A + (size_t)(row0 + r) * K + k0 + kc);
            uint4 t;
            t.x = f2tf32(v.x); t.y = f2tf32(v.y); t.z = f2tf32(v.z); t.w = f2tf32(v.w);
            *(uint4*)&As[r * ASTR + kc] = t;
        }
        // load B tile 32x128
        #pragma unroll
        for (int it = 0; it < 4; it++) {
            int i = it * 256 + tid;
            int kr = i >> 5;
            int nc = (i & 31) * 4;
            float4 v = *(const float4*)(B + (size_t)(k0 + kr) * N + col0 + nc);
            uint4 t;
            t.x = f2tf32(v.x); t.y = f2tf32(v.y); t.z = f2tf32(v.z); t.w = f2tf32(v.w);
            *(uint4*)&Bs[kr * BSTR + nc] = t;
        }
        __syncthreads();

        #pragma unroll
        for (int ks = 0; ks < 4; ks++) {
            int kb = ks * 8;
            uint32_t af[4][4];
            #pragma unroll
            for (int mt = 0; mt < 4; mt++) {
                int r = warp_m * 64 + mt * 16 + grp;
                af[mt][0] = As[r * ASTR + kb + thr];
                af[mt][1] = As[(r + 8) * ASTR + kb + thr];
                af[mt][2] = As[r * ASTR + kb + 4 + thr];
                af[mt][3] = As[(r + 8) * ASTR + kb + 4 + thr];
            }
            uint32_t bf[4][2];
            #pragma unroll
            for (int nt = 0; nt < 4; nt++) {
                int cc = warp_n * 32 + nt * 8 + grp;
                bf[nt][0] = Bs[(kb + thr) * BSTR + cc];
                bf[nt][1] = Bs[(kb + thr + 4) * BSTR + cc];
            }
            #pragma unroll
            for (int mt = 0; mt < 4; mt++)
                #pragma unroll
                for (int nt = 0; nt < 4; nt++) {
                    asm("mma.sync.aligned.m16n8k8.row.col.f32.tf32.tf32.f32 "
                        "{%0,%1,%2,%3}, {%4,%5,%6,%7}, {%8,%9}, {%0,%1,%2,%3};"
                        : "+f"(c[mt][nt][0]), "+f"(c[mt][nt][1]),
                          "+f"(c[mt][nt][2]), "+f"(c[mt][nt][3])
                        : "r"(af[mt][0]), "r"(af[mt][1]), "r"(af[mt][2]), "r"(af[mt][3]),
                          "r"(bf[nt][0]), "r"(bf[nt][1]));
                }
        }
        __syncthreads();
    }

    // epilogue
    #pragma unroll
    for (int mt = 0; mt < 4; mt++) {
        int r = row0 + warp_m * 64 + mt * 16 + grp;
        #pragma unroll
        for (int nt = 0; nt < 4; nt++) {
            int cc = col0 + warp_n * 32 + nt * 8 + 2 * thr;
            float b0 = bias[cc], b1 = bias[cc + 1];
            float o0 = c[mt][nt][0] + b0, o1 = c[mt][nt][1] + b1;
            float o2 = c[mt][nt][2] + b0, o3 = c[mt][nt][3] + b1;
            if (RELU) {
                o0 = fmaxf(o0, 0.f); o1 = fmaxf(o1, 0.f);
                o2 = fmaxf(o2, 0.f); o3 = fmaxf(o3, 0.f);
            }
            if (RES) {
                const float* rp0 = res + (size_t)r * N + cc;
                const float* rp1 = res + (size_t)(r + 8) * N + cc;
                o0 += rp0[0]; o1 += rp0[1];
                o2 += rp1[0]; o3 += rp1[1];
            }
            float2 w0 = make_float2(o0, o1);
            float2 w1 = make_float2(o2, o3);
            *(float2*)&C[(size_t)r * N + cc] = w0;
            *(float2*)&C[(size_t)(r + 8) * N + cc] = w1;
        }
    }
}

// ============================ Flash attention (fp32, f32x2 FMA) ============================
// grid: (S/64, H, B), 256 threads. Thread t: query row r=t/4, subgroup c0=t%4.
// Q row held in registers (64 floats); Ps aliases the Qs tile.
__global__ void attn_kernel(const float* __restrict__ Q,
                            const float* __restrict__ Kp,
                            const float* __restrict__ V,
                            const int*   __restrict__ am,
                            float* __restrict__ O) {
    extern __shared__ float sm[];
    float* Qs = sm;                // [64][AST] -> reused as Ps after Q regs loaded
    float* Ks = Qs + 64 * AST;     // [64][AST]
    float* Vs = Ks + 64 * AST;     // [64][AST]
    float* Ps = Qs;

    int tid = threadIdx.x;
    int q0 = blockIdx.x * 64;
    int h  = blockIdx.y;
    int b  = blockIdx.z;
    int r  = tid >> 2;
    int c0 = tid & 3;
    int cg = c0 * 16;

    // stage Q tile through smem, then pull the full row into registers
    {
        const float* src = Q + ((size_t)(b * Ss + q0 + r)) * Dm + h * HDm + cg;
        float* dst = Qs + r * AST + cg;
        #pragma unroll
        for (int i = 0; i < 16; i += 4) *(float4*)(dst + i) = *(const float4*)(src + i);
    }
    __syncthreads();
    float2 qv[32];
    {
        const float2* qr = (const float2*)(Qs + r * AST);
        #pragma unroll
        for (int i = 0; i < 32; i++) qv[i] = qr[i];
    }
    __syncthreads();   // everyone has Q in regs; Qs can now be reused as Ps

    float2 acc2[8];
    #pragma unroll
    for (int i = 0; i < 8; i++) acc2[i] = make_float2(0.f, 0.f);
    float m = -INFINITY, l = 0.f;
    int qg = q0 + r;

    int ktiles = blockIdx.x + 1;  // causal
    for (int kt = 0; kt < ktiles; kt++) {
        int k0 = kt * 64;
        {
            const float* ks = Kp + ((size_t)(b * Ss + k0 + r)) * Dm + h * HDm + cg;
            const float* vs = V  + ((size_t)(b * Ss + k0 + r)) * Dm + h * HDm + cg;
            float* kd = Ks + r * AST + cg;
            float* vd = Vs + r * AST + cg;
            #pragma unroll
            for (int i = 0; i < 16; i += 4) {
                *(float4*)(kd + i) = *(const float4*)(ks + i);
                *(float4*)(vd + i) = *(const float4*)(vs + i);
            }
        }
        __syncthreads();

        // scores for owned 16 interleaved columns j = c0 + 4*jj
        float s[16];
        #pragma unroll
        for (int jj = 0; jj < 16; jj++) {
            int j = c0 + 4 * jj;
            const float2* kr = (const float2*)(Ks + j * AST);
            float2 a2 = make_float2(0.f, 0.f);
            #pragma unroll
            for (int kk = 0; kk < 32; kk++)
                a2 = fma2(qv[kk], kr[kk], a2);
            float a = a2.x + a2.y;
            int kg = k0 + j;
            bool keep = (kg <= qg) && (am[b * Ss + kg] != 0);
            s[jj] = keep ? a * 0.125f : -INFINITY;
        }

        float tmax = s[0];
        #pragma unroll
        for (int jj = 1; jj < 16; jj++) tmax = fmaxf(tmax, s[jj]);
        tmax = fmaxf(tmax, __shfl_xor_sync(0xffffffffu, tmax, 1));
        tmax = fmaxf(tmax, __shfl_xor_sync(0xffffffffu, tmax, 2));

        float m_new = fmaxf(m, tmax);
        float alpha = (m_new == -INFINITY) ? 1.f : expf(m - m_new);

        float psum = 0.f;
        #pragma unroll
        for (int jj = 0; jj < 16; jj++) {
            float p = (m_new == -INFINITY) ? 0.f : expf(s[jj] - m_new);
            Ps[r * AST + c0 + 4 * jj] = p;
            psum += p;
        }
        psum += __shfl_xor_sync(0xffffffffu, psum, 1);
        psum += __shfl_xor_sync(0xffffffffu, psum, 2);
        l = l * alpha + psum;
        m = m_new;
        float2 al2 = make_float2(alpha, alpha);
        #pragma unroll
        for (int i = 0; i < 8; i++) {
            acc2[i].x *= al2.x; acc2[i].y *= al2.y;
        }
        __syncwarp();   // Ps row written by the 4 lanes of this warp sharing r

        // acc += P @ V for owned head-dims
        #pragma unroll 4
        for (int j = 0; j < 64; j++) {
            float p = Ps[r * AST + j];
            float2 p2 = make_float2(p, p);
            const float2* vr = (const float2*)(Vs + j * AST + cg);
            #pragma unroll
            for (int i = 0; i < 8; i++)
                acc2[i] = fma2(p2, vr[i], acc2[i]);
        }
        __syncthreads();
    }

    float rl = (l > 0.f) ? 1.f / l : 0.f;
    float* op = O + ((size_t)(b * Ss + q0 + r)) * Dm + h * HDm + cg;
    #pragma unroll
    for (int i = 0; i < 8; i++) {
        op[2 * i]     = acc2[i].x * rl;
        op[2 * i + 1] = acc2[i].y * rl;
    }
}

// ============================ launch ============================
extern "C" void kernel_launch(void* const* d_in, const int* in_sizes, int n_in,
                              void* d_out, int out_size) {
    const float* x     = (const float*)d_in[0];
    const int*   am    = (const int*)  d_in[1];
    const float* ln1_g = (const float*)d_in[2];
    const float* ln1_b = (const float*)d_in[3];
    const float* ln2_g = (const float*)d_in[4];
    const float* ln2_b = (const float*)d_in[5];
    const float* Wq = (const float*)d_in[6];
    const float* bq = (const float*)d_in[7];
    const float* Wk = (const float*)d_in[8];
    const float* bk = (const float*)d_in[9];
    const float* Wv = (const float*)d_in[10];
    const float* bv = (const float*)d_in[11];
    const float* Wo = (const float*)d_in[12];
    const float* bo = (const float*)d_in[13];
    const float* W1 = (const float*)d_in[14];
    const float* b1 = (const float*)d_in[15];
    const float* W2 = (const float*)d_in[16];
    const float* b2 = (const float*)d_in[17];
    float* out = (float*)d_out;

    float *h, *q, *k, *v, *ctx, *x1, *h2, *ff1;
    cudaGetSymbolAddress((void**)&h,   g_h);
    cudaGetSymbolAddress((void**)&q,   g_q);
    cudaGetSymbolAddress((void**)&k,   g_k);
    cudaGetSymbolAddress((void**)&v,   g_v);
    cudaGetSymbolAddress((void**)&ctx, g_ctx);
    cudaGetSymbolAddress((void**)&x1,  g_x1);
    cudaGetSymbolAddress((void**)&h2,  g_h2);
    cudaGetSymbolAddress((void**)&ff1, g_ff1);

    // LN1
    ln_kernel<<<NT, 256>>>(x, ln1_g, ln1_b, h);

    // QKV projections (TF32 tensor cores)
    dim3 gD(Dm / 128, NT / 128);
    tf32gemm_kernel<false, false><<<gD, 256>>>(h, Wq, bq, nullptr, q, NT, Dm, Dm);
    tf32gemm_kernel<false, false><<<gD, 256>>>(h, Wk, bk, nullptr, k, NT, Dm, Dm);
    tf32gemm_kernel<false, false><<<gD, 256>>>(h, Wv, bv, nullptr, v, NT, Dm, Dm);

    // attention
    const int ATTN_SMEM = 3 * 64 * AST * 4;
    cudaFuncSetAttribute(attn_kernel, cudaFuncAttributeMaxDynamicSharedMemorySize, ATTN_SMEM);
    attn_kernel<<<dim3(Ss / 64, Hh, Bb), 256, ATTN_SMEM>>>(q, k, v, am, ctx);

    // output projection + residual(x)
    tf32gemm_kernel<false, true><<<gD, 256>>>(ctx, Wo, bo, x, x1, NT, Dm, Dm);

    // LN2
    ln_kernel<<<NT, 256>>>(x1, ln2_g, ln2_b, h2);

    // FFN
    tf32gemm_kernel<true, false><<<dim3(DFFm / 128, NT / 128), 256>>>(h2, W1, b1, nullptr, ff1, NT, DFFm, Dm);
    tf32gemm_kernel<false, true><<<gD, 256>>>(ff1, W2, b2, x1, out, NT, Dm, DFFm);
}

// round 4
// speedup vs baseline: 4.8613x; 3.6615x over previous
#include <cuda_runtime.h>
#include <math.h>
#include <stdint.h>

#define Dm   768
#define Hh   12
#define HDm  64
#define DFFm 3072
#define Bb   2
#define Ss   4096
#define NT   (Bb*Ss)   // 8192 token rows

// ---- scratch (device globals; no allocation allowed) ----
__device__ float g_h  [NT*Dm];
__device__ float g_q  [NT*Dm];
__device__ float g_k  [NT*Dm];
__device__ float g_v  [NT*Dm];
__device__ float g_ctx[NT*Dm];
__device__ float g_x1 [NT*Dm];
__device__ float g_h2 [NT*Dm];
__device__ float g_ff1[NT*DFFm];

// ---------- helpers ----------
__device__ __forceinline__ uint32_t f2tf32(float f) {
    uint32_t r;
    asm("cvt.rna.tf32.f32 %0, %1;" : "=r"(r) : "f"(f));
    return r;
}

// ============================ LayerNorm ============================
__global__ void ln_kernel(const float* __restrict__ x,
                          const float* __restrict__ g,
                          const float* __restrict__ b,
                          float* __restrict__ out) {
    int row = blockIdx.x;
    const float* xr = x + (size_t)row * Dm;
    int tid = threadIdx.x;
    float v0 = xr[tid], v1 = xr[tid + 256], v2 = xr[tid + 512];
    float s  = v0 + v1 + v2;
    float s2 = v0*v0 + v1*v1 + v2*v2;
    #pragma unroll
    for (int o = 16; o; o >>= 1) {
        s  += __shfl_xor_sync(0xffffffffu, s,  o);
        s2 += __shfl_xor_sync(0xffffffffu, s2, o);
    }
    __shared__ float ws[8], ws2[8];
    int w = tid >> 5, l = tid & 31;
    if (l == 0) { ws[w] = s; ws2[w] = s2; }
    __syncthreads();
    __shared__ float smu, srs;
    if (w == 0) {
        s  = (l < 8) ? ws[l]  : 0.f;
        s2 = (l < 8) ? ws2[l] : 0.f;
        #pragma unroll
        for (int o = 4; o; o >>= 1) {
            s  += __shfl_xor_sync(0xffffffffu, s,  o);
            s2 += __shfl_xor_sync(0xffffffffu, s2, o);
        }
        if (l == 0) {
            float mu  = s / Dm;
            float var = fmaxf(s2 / Dm - mu * mu, 0.f);
            smu = mu;
            srs = rsqrtf(var + 1e-5f);
        }
    }
    __syncthreads();
    float mu = smu, rs = srs;
    float* outr = out + (size_t)row * Dm;
    outr[tid]       = (v0 - mu) * rs * g[tid]       + b[tid];
    outr[tid + 256] = (v1 - mu) * rs * g[tid + 256] + b[tid + 256];
    outr[tid + 512] = (v2 - mu) * rs * g[tid + 512] + b[tid + 512];
}

// ============================ TF32 tensor-core GEMM ============================
#define ASTR 36
#define BSTR 136

template<bool RELU, bool RES>
__global__ void tf32gemm_kernel(const float* __restrict__ A,
                                const float* __restrict__ B,
                                const float* __restrict__ bias,
                                const float* __restrict__ res,
                                float* __restrict__ C,
                                int M, int N, int K) {
    __shared__ uint32_t As[128 * ASTR];
    __shared__ uint32_t Bs[32 * BSTR];

    int tid  = threadIdx.x;
    int lane = tid & 31;
    int warp = tid >> 5;
    int warp_m = warp & 1;
    int warp_n = warp >> 1;
    int grp = lane >> 2;
    int thr = lane & 3;

    int row0 = blockIdx.y * 128;
    int col0 = blockIdx.x * 128;

    float c[4][4][4];
    #pragma unroll
    for (int mt = 0; mt < 4; mt++)
        #pragma unroll
        for (int nt = 0; nt < 4; nt++)
            #pragma unroll
            for (int i = 0; i < 4; i++) c[mt][nt][i] = 0.f;

    for (int k0 = 0; k0 < K; k0 += 32) {
        #pragma unroll
        for (int it = 0; it < 4; it++) {
            int i = it * 256 + tid;
            int r = i >> 3;
            int kc = (i & 7) * 4;
            float4 v = *(const float4*)(A + (size_t)(row0 + r) * K + k0 + kc);
            uint4 t;
            t.x = f2tf32(v.x); t.y = f2tf32(v.y); t.z = f2tf32(v.z); t.w = f2tf32(v.w);
            *(uint4*)&As[r * ASTR + kc] = t;
        }
        #pragma unroll
        for (int it = 0; it < 4; it++) {
            int i = it * 256 + tid;
            int kr = i >> 5;
            int nc = (i & 31) * 4;
            float4 v = *(const float4*)(B + (size_t)(k0 + kr) * N + col0 + nc);
            uint4 t;
            t.x = f2tf32(v.x); t.y = f2tf32(v.y); t.z = f2tf32(v.z); t.w = f2tf32(v.w);
            *(uint4*)&Bs[kr * BSTR + nc] = t;
        }
        __syncthreads();

        #pragma unroll
        for (int ks = 0; ks < 4; ks++) {
            int kb = ks * 8;
            uint32_t af[4][4];
            #pragma unroll
            for (int mt = 0; mt < 4; mt++) {
                int r = warp_m * 64 + mt * 16 + grp;
                af[mt][0] = As[r * ASTR + kb + thr];
                af[mt][1] = As[(r + 8) * ASTR + kb + thr];
                af[mt][2] = As[r * ASTR + kb + 4 + thr];
                af[mt][3] = As[(r + 8) * ASTR + kb + 4 + thr];
            }
            uint32_t bf[4][2];
            #pragma unroll
            for (int nt = 0; nt < 4; nt++) {
                int cc = warp_n * 32 + nt * 8 + grp;
                bf[nt][0] = Bs[(kb + thr) * BSTR + cc];
                bf[nt][1] = Bs[(kb + thr + 4) * BSTR + cc];
            }
            #pragma unroll
            for (int mt = 0; mt < 4; mt++)
                #pragma unroll
                for (int nt = 0; nt < 4; nt++) {
                    asm("mma.sync.aligned.m16n8k8.row.col.f32.tf32.tf32.f32 "
                        "{%0,%1,%2,%3}, {%4,%5,%6,%7}, {%8,%9}, {%0,%1,%2,%3};"
                        : "+f"(c[mt][nt][0]), "+f"(c[mt][nt][1]),
                          "+f"(c[mt][nt][2]), "+f"(c[mt][nt][3])
                        : "r"(af[mt][0]), "r"(af[mt][1]), "r"(af[mt][2]), "r"(af[mt][3]),
                          "r"(bf[nt][0]), "r"(bf[nt][1]));
                }
        }
        __syncthreads();
    }

    #pragma unroll
    for (int mt = 0; mt < 4; mt++) {
        int r = row0 + warp_m * 64 + mt * 16 + grp;
        #pragma unroll
        for (int nt = 0; nt < 4; nt++) {
            int cc = col0 + warp_n * 32 + nt * 8 + 2 * thr;
            float b0 = bias[cc], b1 = bias[cc + 1];
            float o0 = c[mt][nt][0] + b0, o1 = c[mt][nt][1] + b1;
            float o2 = c[mt][nt][2] + b0, o3 = c[mt][nt][3] + b1;
            if (RELU) {
                o0 = fmaxf(o0, 0.f); o1 = fmaxf(o1, 0.f);
                o2 = fmaxf(o2, 0.f); o3 = fmaxf(o3, 0.f);
            }
            if (RES) {
                const float* rp0 = res + (size_t)r * N + cc;
                const float* rp1 = res + (size_t)(r + 8) * N + cc;
                o0 += rp0[0]; o1 += rp0[1];
                o2 += rp1[0]; o3 += rp1[1];
            }
            *(float2*)&C[(size_t)r * N + cc]       = make_float2(o0, o1);
            *(float2*)&C[(size_t)(r + 8) * N + cc] = make_float2(o2, o3);
        }
    }
}

// ============================ TF32 tensor-core flash attention ============================
// grid (S/64, H, B), 128 threads = 4 warps; warp w owns query rows w*16..w*16+15.
// Tiles in smem hold tf32 bit patterns. ST=68 words -> conflict-free row-indexed frag loads.
#define ATS 68

__global__ void attn_tc_kernel(const float* __restrict__ Q,
                               const float* __restrict__ Kp,
                               const float* __restrict__ V,
                               const int*   __restrict__ am,
                               float* __restrict__ O) {
    extern __shared__ uint32_t smx[];
    uint32_t* Qs = smx;                 // [64][ATS]
    uint32_t* Ks = Qs + 64 * ATS;       // [64][ATS]
    uint32_t* Vs = Ks + 64 * ATS;       // [64][ATS]
    uint32_t* Ps = Vs + 64 * ATS;       // [64][ATS] (tf32 bits of P)

    int tid  = threadIdx.x;
    int warp = tid >> 5;
    int lane = tid & 31;
    int grp  = lane >> 2;   // 0..7
    int thr  = lane & 3;    // 0..3

    int q0 = blockIdx.x * 64;
    int h  = blockIdx.y;
    int b  = blockIdx.z;
    int r0 = warp * 16;

    const float* Qbase = Q  + ((size_t)(b * Ss + q0)) * Dm + h * HDm;
    const int*   amb   = am + b * Ss;

    // load Q tile (scaled by 1/sqrt(64)=0.125, converted to tf32)
    for (int i = tid; i < 64 * 16; i += 128) {
        int r = i >> 4, c = (i & 15) * 4;
        float4 v = *(const float4*)(Qbase + (size_t)r * Dm + c);
        uint4 t;
        t.x = f2tf32(v.x * 0.125f); t.y = f2tf32(v.y * 0.125f);
        t.z = f2tf32(v.z * 0.125f); t.w = f2tf32(v.w * 0.125f);
        *(uint4*)&Qs[r * ATS + c] = t;
    }

    float o[8][4];
    #pragma unroll
    for (int nc = 0; nc < 8; nc++)
        #pragma unroll
        for (int i = 0; i < 4; i++) o[nc][i] = 0.f;
    float m0 = -INFINITY, m1 = -INFINITY, l0 = 0.f, l1 = 0.f;

    int qg0 = q0 + r0 + grp;
    int qg1 = qg0 + 8;

    int ktiles = blockIdx.x + 1;  // causal
    for (int kt = 0; kt < ktiles; kt++) {
        int k0 = kt * 64;
        const float* Kb = Kp + ((size_t)(b * Ss + k0)) * Dm + h * HDm;
        const float* Vb = V  + ((size_t)(b * Ss + k0)) * Dm + h * HDm;
        if (kt > 0) __syncthreads();   // protect Ks/Vs from previous iter readers
        for (int i = tid; i < 64 * 16; i += 128) {
            int r = i >> 4, c = (i & 15) * 4;
            float4 kv = *(const float4*)(Kb + (size_t)r * Dm + c);
            float4 vv = *(const float4*)(Vb + (size_t)r * Dm + c);
            uint4 tk, tv;
            tk.x = f2tf32(kv.x); tk.y = f2tf32(kv.y); tk.z = f2tf32(kv.z); tk.w = f2tf32(kv.w);
            tv.x = f2tf32(vv.x); tv.y = f2tf32(vv.y); tv.z = f2tf32(vv.z); tv.w = f2tf32(vv.w);
            *(uint4*)&Ks[r * ATS + c] = tk;
            *(uint4*)&Vs[r * ATS + c] = tv;
        }
        __syncthreads();

        // ---- S = Q K^T (warp computes 16x64) ----
        float s[8][4];
        #pragma unroll
        for (int nc = 0; nc < 8; nc++)
            #pragma unroll
            for (int i = 0; i < 4; i++) s[nc][i] = 0.f;

        #pragma unroll
        for (int ks = 0; ks < 8; ks++) {
            int kb = ks * 8;
            uint32_t a0 = Qs[(r0 + grp) * ATS + kb + thr];
            uint32_t a1 = Qs[(r0 + grp + 8) * ATS + kb + thr];
            uint32_t a2 = Qs[(r0 + grp) * ATS + kb + thr + 4];
            uint32_t a3 = Qs[(r0 + grp + 8) * ATS + kb + thr + 4];
            #pragma unroll
            for (int nc = 0; nc < 8; nc++) {
                uint32_t b0 = Ks[(nc * 8 + grp) * ATS + kb + thr];
                uint32_t b1 = Ks[(nc * 8 + grp) * ATS + kb + thr + 4];
                asm("mma.sync.aligned.m16n8k8.row.col.f32.tf32.tf32.f32 "
                    "{%0,%1,%2,%3}, {%4,%5,%6,%7}, {%8,%9}, {%0,%1,%2,%3};"
                    : "+f"(s[nc][0]), "+f"(s[nc][1]), "+f"(s[nc][2]), "+f"(s[nc][3])
                    : "r"(a0), "r"(a1), "r"(a2), "r"(a3), "r"(b0), "r"(b1));
            }
        }

        // ---- mask ----
        #pragma unroll
        for (int nc = 0; nc < 8; nc++) {
            int ca = k0 + nc * 8 + 2 * thr;
            int cb = ca + 1;
            bool va = (amb[ca] != 0), vb = (amb[cb] != 0);
            if (!(ca <= qg0 && va)) s[nc][0] = -INFINITY;
            if (!(cb <= qg0 && vb)) s[nc][1] = -INFINITY;
            if (!(ca <= qg1 && va)) s[nc][2] = -INFINITY;
            if (!(cb <= qg1 && vb)) s[nc][3] = -INFINITY;
        }

        // ---- online softmax (rows grp / grp+8, shared by lane quad) ----
        float t0 = -INFINITY, t1 = -INFINITY;
        #pragma unroll
        for (int nc = 0; nc < 8; nc++) {
            t0 = fmaxf(t0, fmaxf(s[nc][0], s[nc][1]));
            t1 = fmaxf(t1, fmaxf(s[nc][2], s[nc][3]));
        }
        t0 = fmaxf(t0, __shfl_xor_sync(0xffffffffu, t0, 1));
        t0 = fmaxf(t0, __shfl_xor_sync(0xffffffffu, t0, 2));
        t1 = fmaxf(t1, __shfl_xor_sync(0xffffffffu, t1, 1));
        t1 = fmaxf(t1, __shfl_xor_sync(0xffffffffu, t1, 2));

        float mn0 = fmaxf(m0, t0), mn1 = fmaxf(m1, t1);
        float al0 = (mn0 == -INFINITY) ? 1.f : __expf(m0 - mn0);
        float al1 = (mn1 == -INFINITY) ? 1.f : __expf(m1 - mn1);

        float ps0 = 0.f, ps1 = 0.f;
        #pragma unroll
        for (int nc = 0; nc < 8; nc++) {
            float p0 = (s[nc][0] == -INFINITY) ? 0.f : __expf(s[nc][0] - mn0);
            float p1 = (s[nc][1] == -INFINITY) ? 0.f : __expf(s[nc][1] - mn0);
            float p2 = (s[nc][2] == -INFINITY) ? 0.f : __expf(s[nc][2] - mn1);
            float p3 = (s[nc][3] == -INFINITY) ? 0.f : __expf(s[nc][3] - mn1);
            ps0 += p0 + p1;
            ps1 += p2 + p3;
            uint2 w0 = make_uint2(f2tf32(p0), f2tf32(p1));
            uint2 w1 = make_uint2(f2tf32(p2), f2tf32(p3));
            *(uint2*)&Ps[(r0 + grp) * ATS + nc * 8 + 2 * thr]     = w0;
            *(uint2*)&Ps[(r0 + grp + 8) * ATS + nc * 8 + 2 * thr] = w1;
        }
        ps0 += __shfl_xor_sync(0xffffffffu, ps0, 1);
        ps0 += __shfl_xor_sync(0xffffffffu, ps0, 2);
        ps1 += __shfl_xor_sync(0xffffffffu, ps1, 1);
        ps1 += __shfl_xor_sync(0xffffffffu, ps1, 2);

        l0 = l0 * al0 + ps0;
        l1 = l1 * al1 + ps1;
        m0 = mn0; m1 = mn1;

        #pragma unroll
        for (int nc = 0; nc < 8; nc++) {
            o[nc][0] *= al0; o[nc][1] *= al0;
            o[nc][2] *= al1; o[nc][3] *= al1;
        }
        __syncwarp();   // Ps rows r0..r0+15 are warp-local

        // ---- O += P V (warp computes 16x64) ----
        #pragma unroll
        for (int ks = 0; ks < 8; ks++) {
            int kb = ks * 8;
            uint32_t a0 = Ps[(r0 + grp) * ATS + kb + thr];
            uint32_t a1 = Ps[(r0 + grp + 8) * ATS + kb + thr];
            uint32_t a2 = Ps[(r0 + grp) * ATS + kb + thr + 4];
            uint32_t a3 = Ps[(r0 + grp + 8) * ATS + kb + thr + 4];
            #pragma unroll
            for (int nc = 0; nc < 8; nc++) {
                uint32_t b0 = Vs[(kb + thr) * ATS + nc * 8 + grp];
                uint32_t b1 = Vs[(kb + thr + 4) * ATS + nc * 8 + grp];
                asm("mma.sync.aligned.m16n8k8.row.col.f32.tf32.tf32.f32 "
                    "{%0,%1,%2,%3}, {%4,%5,%6,%7}, {%8,%9}, {%0,%1,%2,%3};"
                    : "+f"(o[nc][0]), "+f"(o[nc][1]), "+f"(o[nc][2]), "+f"(o[nc][3])
                    : "r"(a0), "r"(a1), "r"(a2), "r"(a3), "r"(b0), "r"(b1));
            }
        }
    }

    float rl0 = (l0 > 0.f) ? 1.f / l0 : 0.f;
    float rl1 = (l1 > 0.f) ? 1.f / l1 : 0.f;
    float* Ob = O + ((size_t)(b * Ss + q0)) * Dm + h * HDm;
    #pragma unroll
    for (int nc = 0; nc < 8; nc++) {
        int cc = nc * 8 + 2 * thr;
        *(float2*)(Ob + (size_t)(r0 + grp) * Dm + cc)     = make_float2(o[nc][0] * rl0, o[nc][1] * rl0);
        *(float2*)(Ob + (size_t)(r0 + grp + 8) * Dm + cc) = make_float2(o[nc][2] * rl1, o[nc][3] * rl1);
    }
}

// ============================ launch ============================
extern "C" void kernel_launch(void* const* d_in, const int* in_sizes, int n_in,
                              void* d_out, int out_size) {
    const float* x     = (const float*)d_in[0];
    const int*   am    = (const int*)  d_in[1];
    const float* ln1_g = (const float*)d_in[2];
    const float* ln1_b = (const float*)d_in[3];
    const float* ln2_g = (const float*)d_in[4];
    const float* ln2_b = (const float*)d_in[5];
    const float* Wq = (const float*)d_in[6];
    const float* bq = (const float*)d_in[7];
    const float* Wk = (const float*)d_in[8];
    const float* bk = (const float*)d_in[9];
    const float* Wv = (const float*)d_in[10];
    const float* bv = (const float*)d_in[11];
    const float* Wo = (const float*)d_in[12];
    const float* bo = (const float*)d_in[13];
    const float* W1 = (const float*)d_in[14];
    const float* b1 = (const float*)d_in[15];
    const float* W2 = (const float*)d_in[16];
    const float* b2 = (const float*)d_in[17];
    float* out = (float*)d_out;

    float *h, *q, *k, *v, *ctx, *x1, *h2, *ff1;
    cudaGetSymbolAddress((void**)&h,   g_h);
    cudaGetSymbolAddress((void**)&q,   g_q);
    cudaGetSymbolAddress((void**)&k,   g_k);
    cudaGetSymbolAddress((void**)&v,   g_v);
    cudaGetSymbolAddress((void**)&ctx, g_ctx);
    cudaGetSymbolAddress((void**)&x1,  g_x1);
    cudaGetSymbolAddress((void**)&h2,  g_h2);
    cudaGetSymbolAddress((void**)&ff1, g_ff1);

    ln_kernel<<<NT, 256>>>(x, ln1_g, ln1_b, h);

    dim3 gD(Dm / 128, NT / 128);
    tf32gemm_kernel<false, false><<<gD, 256>>>(h, Wq, bq, nullptr, q, NT, Dm, Dm);
    tf32gemm_kernel<false, false><<<gD, 256>>>(h, Wk, bk, nullptr, k, NT, Dm, Dm);
    tf32gemm_kernel<false, false><<<gD, 256>>>(h, Wv, bv, nullptr, v, NT, Dm, Dm);

    const int ATTN_SMEM = 4 * 64 * ATS * 4;   // 69632 B
    cudaFuncSetAttribute(attn_tc_kernel, cudaFuncAttributeMaxDynamicSharedMemorySize, ATTN_SMEM);
    attn_tc_kernel<<<dim3(Ss / 64, Hh, Bb), 128, ATTN_SMEM>>>(q, k, v, am, ctx);

    tf32gemm_kernel<false, true><<<gD, 256>>>(ctx, Wo, bo, x, x1, NT, Dm, Dm);

    ln_kernel<<<NT, 256>>>(x1, ln2_g, ln2_b, h2);

    tf32gemm_kernel<true, false><<<dim3(DFFm / 128, NT / 128), 256>>>(h2, W1, b1, nullptr, ff1, NT, DFFm, Dm);
    tf32gemm_kernel<false, true><<<gD, 256>>>(ff1, W2, b2, x1, out, NT, Dm, DFFm);
}

// round 5
// speedup vs baseline: 5.3184x; 1.0940x over previous
#include <cuda_runtime.h>
#include <math.h>
#include <stdint.h>

#define Dm   768
#define Hh   12
#define HDm  64
#define DFFm 3072
#define Bb   2
#define Ss   4096
#define NT   (Bb*Ss)   // 8192 token rows

// ---- scratch (device globals; no allocation allowed) ----
__device__ float g_h  [NT*Dm];
__device__ float g_q  [NT*Dm];
__device__ float g_k  [NT*Dm];
__device__ float g_v  [NT*Dm];
__device__ float g_ctx[NT*Dm];
__device__ float g_x1 [NT*Dm];
__device__ float g_h2 [NT*Dm];
__device__ float g_ff1[NT*DFFm];

// ---------- helpers ----------
__device__ __forceinline__ uint32_t f2tf32(float f) {
    uint32_t r;
    asm("cvt.rna.tf32.f32 %0, %1;" : "=r"(r) : "f"(f));
    return r;
}

__device__ __forceinline__ void cp_async16(void* smem, const void* gmem) {
    uint32_t s = (uint32_t)__cvta_generic_to_shared(smem);
    asm volatile("cp.async.cg.shared.global [%0], [%1], 16;" :: "r"(s), "l"(gmem));
}

// ============================ LayerNorm ============================
__global__ void ln_kernel(const float* __restrict__ x,
                          const float* __restrict__ g,
                          const float* __restrict__ b,
                          float* __restrict__ out) {
    int row = blockIdx.x;
    const float* xr = x + (size_t)row * Dm;
    int tid = threadIdx.x;
    float v0 = xr[tid], v1 = xr[tid + 256], v2 = xr[tid + 512];
    float s  = v0 + v1 + v2;
    float s2 = v0*v0 + v1*v1 + v2*v2;
    #pragma unroll
    for (int o = 16; o; o >>= 1) {
        s  += __shfl_xor_sync(0xffffffffu, s,  o);
        s2 += __shfl_xor_sync(0xffffffffu, s2, o);
    }
    __shared__ float ws[8], ws2[8];
    int w = tid >> 5, l = tid & 31;
    if (l == 0) { ws[w] = s; ws2[w] = s2; }
    __syncthreads();
    __shared__ float smu, srs;
    if (w == 0) {
        s  = (l < 8) ? ws[l]  : 0.f;
        s2 = (l < 8) ? ws2[l] : 0.f;
        #pragma unroll
        for (int o = 4; o; o >>= 1) {
            s  += __shfl_xor_sync(0xffffffffu, s,  o);
            s2 += __shfl_xor_sync(0xffffffffu, s2, o);
        }
        if (l == 0) {
            float mu  = s / Dm;
            float var = fmaxf(s2 / Dm - mu * mu, 0.f);
            smu = mu;
            srs = rsqrtf(var + 1e-5f);
        }
    }
    __syncthreads();
    float mu = smu, rs = srs;
    float* outr = out + (size_t)row * Dm;
    outr[tid]       = (v0 - mu) * rs * g[tid]       + b[tid];
    outr[tid + 256] = (v1 - mu) * rs * g[tid + 256] + b[tid + 256];
    outr[tid + 512] = (v2 - mu) * rs * g[tid + 512] + b[tid + 512];
}

// ============================ TF32 tensor-core GEMM (cp.async 2-stage) ============================
#define ASTR 36
#define BSTR 136
#define A_WORDS (128 * ASTR)
#define B_WORDS (32 * BSTR)
#define GEMM_SMEM (2 * (A_WORDS + B_WORDS) * 4)

template<bool RELU, bool RES>
__global__ void tf32gemm_kernel(const float* __restrict__ A,
                                const float* __restrict__ B,
                                const float* __restrict__ bias,
                                const float* __restrict__ res,
                                float* __restrict__ C,
                                int M, int N, int K) {
    extern __shared__ uint32_t sh[];
    uint32_t* AsBase = sh;                    // [2][A_WORDS]
    uint32_t* BsBase = sh + 2 * A_WORDS;      // [2][B_WORDS]

    int tid  = threadIdx.x;
    int lane = tid & 31;
    int warp = tid >> 5;
    int warp_m = warp & 1;
    int warp_n = warp >> 1;
    int grp = lane >> 2;
    int thr = lane & 3;

    int row0 = blockIdx.y * 128;
    int col0 = blockIdx.x * 128;

    // per-thread load coordinates (fixed across tiles)
    int ar = tid >> 1;             // A row (2 threads per row, 4 words each... )
    // A tile: 128 rows x 32 cols, 16B chunks: 128*8 = 1024 chunks, 256 threads -> 4 each
    // chunk i: r = i>>3, kc = (i&7)*4
    // B tile: 32 rows x 128 cols: 32*32 = 1024 chunks; kr = i>>5, nc = (i&31)*4
    (void)ar;

    float c[4][4][4];
    #pragma unroll
    for (int mt = 0; mt < 4; mt++)
        #pragma unroll
        for (int nt = 0; nt < 4; nt++)
            #pragma unroll
            for (int i = 0; i < 4; i++) c[mt][nt][i] = 0.f;

    auto load_tile = [&](int k0, int stg) {
        uint32_t* Ad = AsBase + stg * A_WORDS;
        uint32_t* Bd = BsBase + stg * B_WORDS;
        #pragma unroll
        for (int it = 0; it < 4; it++) {
            int i = it * 256 + tid;
            int r = i >> 3, kc = (i & 7) * 4;
            cp_async16(&Ad[r * ASTR + kc], A + (size_t)(row0 + r) * K + k0 + kc);
        }
        #pragma unroll
        for (int it = 0; it < 4; it++) {
            int i = it * 256 + tid;
            int kr = i >> 5, nc = (i & 31) * 4;
            cp_async16(&Bd[kr * BSTR + nc], B + (size_t)(k0 + kr) * N + col0 + nc);
        }
        asm volatile("cp.async.commit_group;" ::: "memory");
    };

    int NK = K >> 5;
    load_tile(0, 0);

    for (int i = 0; i < NK; i++) {
        if (i + 1 < NK) {
            load_tile((i + 1) << 5, (i + 1) & 1);
            asm volatile("cp.async.wait_group 1;" ::: "memory");
        } else {
            asm volatile("cp.async.wait_group 0;" ::: "memory");
        }
        __syncthreads();

        const uint32_t* As = AsBase + (i & 1) * A_WORDS;
        const uint32_t* Bs = BsBase + (i & 1) * B_WORDS;

        #pragma unroll
        for (int ks = 0; ks < 4; ks++) {
            int kb = ks * 8;
            uint32_t af[4][4];
            #pragma unroll
            for (int mt = 0; mt < 4; mt++) {
                int r = warp_m * 64 + mt * 16 + grp;
                af[mt][0] = As[r * ASTR + kb + thr];
                af[mt][1] = As[(r + 8) * ASTR + kb + thr];
                af[mt][2] = As[r * ASTR + kb + 4 + thr];
                af[mt][3] = As[(r + 8) * ASTR + kb + 4 + thr];
            }
            uint32_t bf[4][2];
            #pragma unroll
            for (int nt = 0; nt < 4; nt++) {
                int cc = warp_n * 32 + nt * 8 + grp;
                bf[nt][0] = Bs[(kb + thr) * BSTR + cc];
                bf[nt][1] = Bs[(kb + thr + 4) * BSTR + cc];
            }
            #pragma unroll
            for (int mt = 0; mt < 4; mt++)
                #pragma unroll
                for (int nt = 0; nt < 4; nt++) {
                    asm("mma.sync.aligned.m16n8k8.row.col.f32.tf32.tf32.f32 "
                        "{%0,%1,%2,%3}, {%4,%5,%6,%7}, {%8,%9}, {%0,%1,%2,%3};"
                        : "+f"(c[mt][nt][0]), "+f"(c[mt][nt][1]),
                          "+f"(c[mt][nt][2]), "+f"(c[mt][nt][3])
                        : "r"(af[mt][0]), "r"(af[mt][1]), "r"(af[mt][2]), "r"(af[mt][3]),
                          "r"(bf[nt][0]), "r"(bf[nt][1]));
                }
        }
        __syncthreads();
    }

    #pragma unroll
    for (int mt = 0; mt < 4; mt++) {
        int r = row0 + warp_m * 64 + mt * 16 + grp;
        #pragma unroll
        for (int nt = 0; nt < 4; nt++) {
            int cc = col0 + warp_n * 32 + nt * 8 + 2 * thr;
            float b0 = bias[cc], b1 = bias[cc + 1];
            float o0 = c[mt][nt][0] + b0, o1 = c[mt][nt][1] + b1;
            float o2 = c[mt][nt][2] + b0, o3 = c[mt][nt][3] + b1;
            if (RELU) {
                o0 = fmaxf(o0, 0.f); o1 = fmaxf(o1, 0.f);
                o2 = fmaxf(o2, 0.f); o3 = fmaxf(o3, 0.f);
            }
            if (RES) {
                const float* rp0 = res + (size_t)r * N + cc;
                const float* rp1 = res + (size_t)(r + 8) * N + cc;
                o0 += rp0[0]; o1 += rp0[1];
                o2 += rp1[0]; o3 += rp1[1];
            }
            *(float2*)&C[(size_t)r * N + cc]       = make_float2(o0, o1);
            *(float2*)&C[(size_t)(r + 8) * N + cc] = make_float2(o2, o3);
        }
    }
}

// ============================ TF32 tensor-core flash attention ============================
#define ATS 68

__global__ void attn_tc_kernel(const float* __restrict__ Q,
                               const float* __restrict__ Kp,
                               const float* __restrict__ V,
                               const int*   __restrict__ am,
                               float* __restrict__ O) {
    extern __shared__ uint32_t smx[];
    uint32_t* Qs = smx;                 // [64][ATS]
    uint32_t* Ks = Qs + 64 * ATS;       // [64][ATS]
    uint32_t* Vs = Ks + 64 * ATS;       // [64][ATS]
    uint32_t* Ps = Vs + 64 * ATS;       // [64][ATS]

    int tid  = threadIdx.x;
    int warp = tid >> 5;
    int lane = tid & 31;
    int grp  = lane >> 2;
    int thr  = lane & 3;

    int q0 = blockIdx.x * 64;
    int h  = blockIdx.y;
    int b  = blockIdx.z;
    int r0 = warp * 16;

    const float* Qbase = Q  + ((size_t)(b * Ss + q0)) * Dm + h * HDm;
    const int*   amb   = am + b * Ss;

    for (int i = tid; i < 64 * 16; i += 128) {
        int r = i >> 4, c = (i & 15) * 4;
        float4 v = *(const float4*)(Qbase + (size_t)r * Dm + c);
        uint4 t;
        t.x = f2tf32(v.x * 0.125f); t.y = f2tf32(v.y * 0.125f);
        t.z = f2tf32(v.z * 0.125f); t.w = f2tf32(v.w * 0.125f);
        *(uint4*)&Qs[r * ATS + c] = t;
    }

    float o[8][4];
    #pragma unroll
    for (int nc = 0; nc < 8; nc++)
        #pragma unroll
        for (int i = 0; i < 4; i++) o[nc][i] = 0.f;
    float m0 = -INFINITY, m1 = -INFINITY, l0 = 0.f, l1 = 0.f;

    int qg0 = q0 + r0 + grp;
    int qg1 = qg0 + 8;

    int ktiles = blockIdx.x + 1;
    for (int kt = 0; kt < ktiles; kt++) {
        int k0 = kt * 64;
        const float* Kb = Kp + ((size_t)(b * Ss + k0)) * Dm + h * HDm;
        const float* Vb = V  + ((size_t)(b * Ss + k0)) * Dm + h * HDm;
        if (kt > 0) __syncthreads();
        for (int i = tid; i < 64 * 16; i += 128) {
            int r = i >> 4, c = (i & 15) * 4;
            float4 kv = *(const float4*)(Kb + (size_t)r * Dm + c);
            float4 vv = *(const float4*)(Vb + (size_t)r * Dm + c);
            uint4 tk, tv;
            tk.x = f2tf32(kv.x); tk.y = f2tf32(kv.y); tk.z = f2tf32(kv.z); tk.w = f2tf32(kv.w);
            tv.x = f2tf32(vv.x); tv.y = f2tf32(vv.y); tv.z = f2tf32(vv.z); tv.w = f2tf32(vv.w);
            *(uint4*)&Ks[r * ATS + c] = tk;
            *(uint4*)&Vs[r * ATS + c] = tv;
        }
        __syncthreads();

        float s[8][4];
        #pragma unroll
        for (int nc = 0; nc < 8; nc++)
            #pragma unroll
            for (int i = 0; i < 4; i++) s[nc][i] = 0.f;

        #pragma unroll
        for (int ks = 0; ks < 8; ks++) {
            int kb = ks * 8;
            uint32_t a0 = Qs[(r0 + grp) * ATS + kb + thr];
            uint32_t a1 = Qs[(r0 + grp + 8) * ATS + kb + thr];
            uint32_t a2 = Qs[(r0 + grp) * ATS + kb + thr + 4];
            uint32_t a3 = Qs[(r0 + grp + 8) * ATS + kb + thr + 4];
            #pragma unroll
            for (int nc = 0; nc < 8; nc++) {
                uint32_t b0 = Ks[(nc * 8 + grp) * ATS + kb + thr];
                uint32_t b1 = Ks[(nc * 8 + grp) * ATS + kb + thr + 4];
                asm("mma.sync.aligned.m16n8k8.row.col.f32.tf32.tf32.f32 "
                    "{%0,%1,%2,%3}, {%4,%5,%6,%7}, {%8,%9}, {%0,%1,%2,%3};"
                    : "+f"(s[nc][0]), "+f"(s[nc][1]), "+f"(s[nc][2]), "+f"(s[nc][3])
                    : "r"(a0), "r"(a1), "r"(a2), "r"(a3), "r"(b0), "r"(b1));
            }
        }

        #pragma unroll
        for (int nc = 0; nc < 8; nc++) {
            int ca = k0 + nc * 8 + 2 * thr;
            int cb = ca + 1;
            bool va = (amb[ca] != 0), vb = (amb[cb] != 0);
            if (!(ca <= qg0 && va)) s[nc][0] = -INFINITY;
            if (!(cb <= qg0 && vb)) s[nc][1] = -INFINITY;
            if (!(ca <= qg1 && va)) s[nc][2] = -INFINITY;
            if (!(cb <= qg1 && vb)) s[nc][3] = -INFINITY;
        }

        float t0 = -INFINITY, t1 = -INFINITY;
        #pragma unroll
        for (int nc = 0; nc < 8; nc++) {
            t0 = fmaxf(t0, fmaxf(s[nc][0], s[nc][1]));
            t1 = fmaxf(t1, fmaxf(s[nc][2], s[nc][3]));
        }
        t0 = fmaxf(t0, __shfl_xor_sync(0xffffffffu, t0, 1));
        t0 = fmaxf(t0, __shfl_xor_sync(0xffffffffu, t0, 2));
        t1 = fmaxf(t1, __shfl_xor_sync(0xffffffffu, t1, 1));
        t1 = fmaxf(t1, __shfl_xor_sync(0xffffffffu, t1, 2));

        float mn0 = fmaxf(m0, t0), mn1 = fmaxf(m1, t1);
        float al0 = (mn0 == -INFINITY) ? 1.f : __expf(m0 - mn0);
        float al1 = (mn1 == -INFINITY) ? 1.f : __expf(m1 - mn1);

        float ps0 = 0.f, ps1 = 0.f;
        #pragma unroll
        for (int nc = 0; nc < 8; nc++) {
            float p0 = (s[nc][0] == -INFINITY) ? 0.f : __expf(s[nc][0] - mn0);
            float p1 = (s[nc][1] == -INFINITY) ? 0.f : __expf(s[nc][1] - mn0);
            float p2 = (s[nc][2] == -INFINITY) ? 0.f : __expf(s[nc][2] - mn1);
            float p3 = (s[nc][3] == -INFINITY) ? 0.f : __expf(s[nc][3] - mn1);
            ps0 += p0 + p1;
            ps1 += p2 + p3;
            *(uint2*)&Ps[(r0 + grp) * ATS + nc * 8 + 2 * thr]     = make_uint2(f2tf32(p0), f2tf32(p1));
            *(uint2*)&Ps[(r0 + grp + 8) * ATS + nc * 8 + 2 * thr] = make_uint2(f2tf32(p2), f2tf32(p3));
        }
        ps0 += __shfl_xor_sync(0xffffffffu, ps0, 1);
        ps0 += __shfl_xor_sync(0xffffffffu, ps0, 2);
        ps1 += __shfl_xor_sync(0xffffffffu, ps1, 1);
        ps1 += __shfl_xor_sync(0xffffffffu, ps1, 2);

        l0 = l0 * al0 + ps0;
        l1 = l1 * al1 + ps1;
        m0 = mn0; m1 = mn1;

        #pragma unroll
        for (int nc = 0; nc < 8; nc++) {
            o[nc][0] *= al0; o[nc][1] *= al0;
            o[nc][2] *= al1; o[nc][3] *= al1;
        }
        __syncwarp();

        #pragma unroll
        for (int ks = 0; ks < 8; ks++) {
            int kb = ks * 8;
            uint32_t a0 = Ps[(r0 + grp) * ATS + kb + thr];
            uint32_t a1 = Ps[(r0 + grp + 8) * ATS + kb + thr];
            uint32_t a2 = Ps[(r0 + grp) * ATS + kb + thr + 4];
            uint32_t a3 = Ps[(r0 + grp + 8) * ATS + kb + thr + 4];
            #pragma unroll
            for (int nc = 0; nc < 8; nc++) {
                uint32_t b0 = Vs[(kb + thr) * ATS + nc * 8 + grp];
                uint32_t b1 = Vs[(kb + thr + 4) * ATS + nc * 8 + grp];
                asm("mma.sync.aligned.m16n8k8.row.col.f32.tf32.tf32.f32 "
                    "{%0,%1,%2,%3}, {%4,%5,%6,%7}, {%8,%9}, {%0,%1,%2,%3};"
                    : "+f"(o[nc][0]), "+f"(o[nc][1]), "+f"(o[nc][2]), "+f"(o[nc][3])
                    : "r"(a0), "r"(a1), "r"(a2), "r"(a3), "r"(b0), "r"(b1));
            }
        }
    }

    float rl0 = (l0 > 0.f) ? 1.f / l0 : 0.f;
    float rl1 = (l1 > 0.f) ? 1.f / l1 : 0.f;
    float* Ob = O + ((size_t)(b * Ss + q0)) * Dm + h * HDm;
    #pragma unroll
    for (int nc = 0; nc < 8; nc++) {
        int cc = nc * 8 + 2 * thr;
        *(float2*)(Ob + (size_t)(r0 + grp) * Dm + cc)     = make_float2(o[nc][0] * rl0, o[nc][1] * rl0);
        *(float2*)(Ob + (size_t)(r0 + grp + 8) * Dm + cc) = make_float2(o[nc][2] * rl1, o[nc][3] * rl1);
    }
}

// ============================ launch ============================
extern "C" void kernel_launch(void* const* d_in, const int* in_sizes, int n_in,
                              void* d_out, int out_size) {
    const float* x     = (const float*)d_in[0];
    const int*   am    = (const int*)  d_in[1];
    const float* ln1_g = (const float*)d_in[2];
    const float* ln1_b = (const float*)d_in[3];
    const float* ln2_g = (const float*)d_in[4];
    const float* ln2_b = (const float*)d_in[5];
    const float* Wq = (const float*)d_in[6];
    const float* bq = (const float*)d_in[7];
    const float* Wk = (const float*)d_in[8];
    const float* bk = (const float*)d_in[9];
    const float* Wv = (const float*)d_in[10];
    const float* bv = (const float*)d_in[11];
    const float* Wo = (const float*)d_in[12];
    const float* bo = (const float*)d_in[13];
    const float* W1 = (const float*)d_in[14];
    const float* b1 = (const float*)d_in[15];
    const float* W2 = (const float*)d_in[16];
    const float* b2 = (const float*)d_in[17];
    float* out = (float*)d_out;

    float *h, *q, *k, *v, *ctx, *x1, *h2, *ff1;
    cudaGetSymbolAddress((void**)&h,   g_h);
    cudaGetSymbolAddress((void**)&q,   g_q);
    cudaGetSymbolAddress((void**)&k,   g_k);
    cudaGetSymbolAddress((void**)&v,   g_v);
    cudaGetSymbolAddress((void**)&ctx, g_ctx);
    cudaGetSymbolAddress((void**)&x1,  g_x1);
    cudaGetSymbolAddress((void**)&h2,  g_h2);
    cudaGetSymbolAddress((void**)&ff1, g_ff1);

    cudaFuncSetAttribute(tf32gemm_kernel<false, false>, cudaFuncAttributeMaxDynamicSharedMemorySize, GEMM_SMEM);
    cudaFuncSetAttribute(tf32gemm_kernel<false, true>,  cudaFuncAttributeMaxDynamicSharedMemorySize, GEMM_SMEM);
    cudaFuncSetAttribute(tf32gemm_kernel<true,  false>, cudaFuncAttributeMaxDynamicSharedMemorySize, GEMM_SMEM);

    ln_kernel<<<NT, 256>>>(x, ln1_g, ln1_b, h);

    dim3 gD(Dm / 128, NT / 128);
    tf32gemm_kernel<false, false><<<gD, 256, GEMM_SMEM>>>(h, Wq, bq, nullptr, q, NT, Dm, Dm);
    tf32gemm_kernel<false, false><<<gD, 256, GEMM_SMEM>>>(h, Wk, bk, nullptr, k, NT, Dm, Dm);
    tf32gemm_kernel<false, false><<<gD, 256, GEMM_SMEM>>>(h, Wv, bv, nullptr, v, NT, Dm, Dm);

    const int ATTN_SMEM = 4 * 64 * ATS * 4;
    cudaFuncSetAttribute(attn_tc_kernel, cudaFuncAttributeMaxDynamicSharedMemorySize, ATTN_SMEM);
    attn_tc_kernel<<<dim3(Ss / 64, Hh, Bb), 128, ATTN_SMEM>>>(q, k, v, am, ctx);

    tf32gemm_kernel<false, true><<<gD, 256, GEMM_SMEM>>>(ctx, Wo, bo, x, x1, NT, Dm, Dm);

    ln_kernel<<<NT, 256>>>(x1, ln2_g, ln2_b, h2);

    tf32gemm_kernel<true, false><<<dim3(DFFm / 128, NT / 128), 256, GEMM_SMEM>>>(h2, W1, b1, nullptr, ff1, NT, DFFm, Dm);
    tf32gemm_kernel<false, true><<<gD, 256, GEMM_SMEM>>>(ff1, W2, b2, x1, out, NT, Dm, DFFm);
}

// round 6
// speedup vs baseline: 5.6676x; 1.0657x over previous
#include <cuda_runtime.h>
#include <math.h>
#include <stdint.h>

#define Dm   768
#define Hh   12
#define HDm  64
#define DFFm 3072
#define Bb   2
#define Ss   4096
#define NT   (Bb*Ss)   // 8192 token rows

// ---- scratch (device globals; no allocation allowed) ----
__device__ float g_h  [NT*Dm];
__device__ float g_q  [NT*Dm];
__device__ float g_k  [NT*Dm];
__device__ float g_v  [NT*Dm];
__device__ float g_ctx[NT*Dm];
__device__ float g_x1 [NT*Dm];
__device__ float g_h2 [NT*Dm];
__device__ float g_ff1[NT*DFFm];
// rounded weight copies: Wq,Wk,Wv,Wo (D*D each), W1 (D*DFF), W2 (DFF*D)
__device__ float g_w  [4*Dm*Dm + 2*Dm*DFFm];

// ---------- helpers ----------
__device__ __forceinline__ uint32_t f2tf32(float f) {
    uint32_t r;
    asm("cvt.rna.tf32.f32 %0, %1;" : "=r"(r) : "f"(f));
    return r;
}
__device__ __forceinline__ float rtf(float f) { return __uint_as_float(f2tf32(f)); }

__device__ __forceinline__ void cp_async16(void* smem, const void* gmem) {
    uint32_t s = (uint32_t)__cvta_generic_to_shared(smem);
    asm volatile("cp.async.cg.shared.global [%0], [%1], 16;" :: "r"(s), "l"(gmem));
}

// ============================ weight rounding pre-pass ============================
__global__ void round_tf32_kernel(const float* __restrict__ src,
                                  float* __restrict__ dst, int n4) {
    int i = blockIdx.x * blockDim.x + threadIdx.x;
    if (i < n4) {
        float4 v = ((const float4*)src)[i];
        v.x = rtf(v.x); v.y = rtf(v.y); v.z = rtf(v.z); v.w = rtf(v.w);
        ((float4*)dst)[i] = v;
    }
}

// ============================ LayerNorm (tf32-rounded output) ============================
__global__ void ln_kernel(const float* __restrict__ x,
                          const float* __restrict__ g,
                          const float* __restrict__ b,
                          float* __restrict__ out) {
    int row = blockIdx.x;
    const float* xr = x + (size_t)row * Dm;
    int tid = threadIdx.x;
    float v0 = xr[tid], v1 = xr[tid + 256], v2 = xr[tid + 512];
    float s  = v0 + v1 + v2;
    float s2 = v0*v0 + v1*v1 + v2*v2;
    #pragma unroll
    for (int o = 16; o; o >>= 1) {
        s  += __shfl_xor_sync(0xffffffffu, s,  o);
        s2 += __shfl_xor_sync(0xffffffffu, s2, o);
    }
    __shared__ float ws[8], ws2[8];
    int w = tid >> 5, l = tid & 31;
    if (l == 0) { ws[w] = s; ws2[w] = s2; }
    __syncthreads();
    __shared__ float smu, srs;
    if (w == 0) {
        s  = (l < 8) ? ws[l]  : 0.f;
        s2 = (l < 8) ? ws2[l] : 0.f;
        #pragma unroll
        for (int o = 4; o; o >>= 1) {
            s  += __shfl_xor_sync(0xffffffffu, s,  o);
            s2 += __shfl_xor_sync(0xffffffffu, s2, o);
        }
        if (l == 0) {
            float mu  = s / Dm;
            float var = fmaxf(s2 / Dm - mu * mu, 0.f);
            smu = mu;
            srs = rsqrtf(var + 1e-5f);
        }
    }
    __syncthreads();
    float mu = smu, rs = srs;
    float* outr = out + (size_t)row * Dm;
    outr[tid]       = rtf((v0 - mu) * rs * g[tid]       + b[tid]);
    outr[tid + 256] = rtf((v1 - mu) * rs * g[tid + 256] + b[tid + 256]);
    outr[tid + 512] = rtf((v2 - mu) * rs * g[tid + 512] + b[tid + 512]);
}

// ============================ TF32 tensor-core GEMM (cp.async 2-stage, 2 CTA/SM) ============================
// Inputs A and B must already be tf32(RNA)-rounded values; raw bits feed mma directly.
#define ASTR 36
#define BSTR 136
#define A_WORDS (128 * ASTR)
#define B_WORDS (32 * BSTR)
#define GEMM_SMEM (2 * (A_WORDS + B_WORDS) * 4)

// RNDC: round C output to tf32 (for ff1, which feeds the next GEMM as A)
template<bool RELU, bool RES, bool RNDC>
__global__ __launch_bounds__(256, 2)
void tf32gemm_kernel(const float* __restrict__ A,
                     const float* __restrict__ B,
                     const float* __restrict__ bias,
                     const float* __restrict__ res,
                     float* __restrict__ C,
                     int M, int N, int K) {
    extern __shared__ uint32_t sh[];
    uint32_t* AsBase = sh;
    uint32_t* BsBase = sh + 2 * A_WORDS;

    int tid  = threadIdx.x;
    int lane = tid & 31;
    int warp = tid >> 5;
    int warp_m = warp & 1;
    int warp_n = warp >> 1;
    int grp = lane >> 2;
    int thr = lane & 3;

    int row0 = blockIdx.y * 128;
    int col0 = blockIdx.x * 128;

    float c[4][4][4];
    #pragma unroll
    for (int mt = 0; mt < 4; mt++)
        #pragma unroll
        for (int nt = 0; nt < 4; nt++)
            #pragma unroll
            for (int i = 0; i < 4; i++) c[mt][nt][i] = 0.f;

    auto load_tile = [&](int k0, int stg) {
        uint32_t* Ad = AsBase + stg * A_WORDS;
        uint32_t* Bd = BsBase + stg * B_WORDS;
        #pragma unroll
        for (int it = 0; it < 4; it++) {
            int i = it * 256 + tid;
            int r = i >> 3, kc = (i & 7) * 4;
            cp_async16(&Ad[r * ASTR + kc], A + (size_t)(row0 + r) * K + k0 + kc);
        }
        #pragma unroll
        for (int it = 0; it < 4; it++) {
            int i = it * 256 + tid;
            int kr = i >> 5, nc = (i & 31) * 4;
            cp_async16(&Bd[kr * BSTR + nc], B + (size_t)(k0 + kr) * N + col0 + nc);
        }
        asm volatile("cp.async.commit_group;" ::: "memory");
    };

    int NK = K >> 5;
    load_tile(0, 0);

    for (int i = 0; i < NK; i++) {
        if (i + 1 < NK) {
            load_tile((i + 1) << 5, (i + 1) & 1);
            asm volatile("cp.async.wait_group 1;" ::: "memory");
        } else {
            asm volatile("cp.async.wait_group 0;" ::: "memory");
        }
        __syncthreads();

        const uint32_t* As = AsBase + (i & 1) * A_WORDS;
        const uint32_t* Bs = BsBase + (i & 1) * B_WORDS;

        #pragma unroll
        for (int ks = 0; ks < 4; ks++) {
            int kb = ks * 8;
            uint32_t af[4][4];
            #pragma unroll
            for (int mt = 0; mt < 4; mt++) {
                int r = warp_m * 64 + mt * 16 + grp;
                af[mt][0] = As[r * ASTR + kb + thr];
                af[mt][1] = As[(r + 8) * ASTR + kb + thr];
                af[mt][2] = As[r * ASTR + kb + 4 + thr];
                af[mt][3] = As[(r + 8) * ASTR + kb + 4 + thr];
            }
            uint32_t bf[4][2];
            #pragma unroll
            for (int nt = 0; nt < 4; nt++) {
                int cc = warp_n * 32 + nt * 8 + grp;
                bf[nt][0] = Bs[(kb + thr) * BSTR + cc];
                bf[nt][1] = Bs[(kb + thr + 4) * BSTR + cc];
            }
            #pragma unroll
            for (int mt = 0; mt < 4; mt++)
                #pragma unroll
                for (int nt = 0; nt < 4; nt++) {
                    asm("mma.sync.aligned.m16n8k8.row.col.f32.tf32.tf32.f32 "
                        "{%0,%1,%2,%3}, {%4,%5,%6,%7}, {%8,%9}, {%0,%1,%2,%3};"
                        : "+f"(c[mt][nt][0]), "+f"(c[mt][nt][1]),
                          "+f"(c[mt][nt][2]), "+f"(c[mt][nt][3])
                        : "r"(af[mt][0]), "r"(af[mt][1]), "r"(af[mt][2]), "r"(af[mt][3]),
                          "r"(bf[nt][0]), "r"(bf[nt][1]));
                }
        }
        __syncthreads();
    }

    #pragma unroll
    for (int mt = 0; mt < 4; mt++) {
        int r = row0 + warp_m * 64 + mt * 16 + grp;
        #pragma unroll
        for (int nt = 0; nt < 4; nt++) {
            int cc = col0 + warp_n * 32 + nt * 8 + 2 * thr;
            float b0 = bias[cc], b1 = bias[cc + 1];
            float o0 = c[mt][nt][0] + b0, o1 = c[mt][nt][1] + b1;
            float o2 = c[mt][nt][2] + b0, o3 = c[mt][nt][3] + b1;
            if (RELU) {
                o0 = fmaxf(o0, 0.f); o1 = fmaxf(o1, 0.f);
                o2 = fmaxf(o2, 0.f); o3 = fmaxf(o3, 0.f);
            }
            if (RES) {
                const float* rp0 = res + (size_t)r * N + cc;
                const float* rp1 = res + (size_t)(r + 8) * N + cc;
                o0 += rp0[0]; o1 += rp0[1];
                o2 += rp1[0]; o3 += rp1[1];
            }
            if (RNDC) {
                o0 = rtf(o0); o1 = rtf(o1); o2 = rtf(o2); o3 = rtf(o3);
            }
            *(float2*)&C[(size_t)r * N + cc]       = make_float2(o0, o1);
            *(float2*)&C[(size_t)(r + 8) * N + cc] = make_float2(o2, o3);
        }
    }
}

// ============================ TF32 tensor-core flash attention ============================
#define ATS 68

__global__ void attn_tc_kernel(const float* __restrict__ Q,
                               const float* __restrict__ Kp,
                               const float* __restrict__ V,
                               const int*   __restrict__ am,
                               float* __restrict__ O) {
    extern __shared__ uint32_t smx[];
    uint32_t* Qs = smx;
    uint32_t* Ks = Qs + 64 * ATS;
    uint32_t* Vs = Ks + 64 * ATS;
    uint32_t* Ps = Vs + 64 * ATS;

    int tid  = threadIdx.x;
    int warp = tid >> 5;
    int lane = tid & 31;
    int grp  = lane >> 2;
    int thr  = lane & 3;

    int q0 = blockIdx.x * 64;
    int h  = blockIdx.y;
    int b  = blockIdx.z;
    int r0 = warp * 16;

    const float* Qbase = Q  + ((size_t)(b * Ss + q0)) * Dm + h * HDm;
    const int*   amb   = am + b * Ss;

    for (int i = tid; i < 64 * 16; i += 128) {
        int r = i >> 4, c = (i & 15) * 4;
        float4 v = *(const float4*)(Qbase + (size_t)r * Dm + c);
        uint4 t;
        t.x = f2tf32(v.x * 0.125f); t.y = f2tf32(v.y * 0.125f);
        t.z = f2tf32(v.z * 0.125f); t.w = f2tf32(v.w * 0.125f);
        *(uint4*)&Qs[r * ATS + c] = t;
    }

    float o[8][4];
    #pragma unroll
    for (int nc = 0; nc < 8; nc++)
        #pragma unroll
        for (int i = 0; i < 4; i++) o[nc][i] = 0.f;
    float m0 = -INFINITY, m1 = -INFINITY, l0 = 0.f, l1 = 0.f;

    int qg0 = q0 + r0 + grp;
    int qg1 = qg0 + 8;

    int ktiles = blockIdx.x + 1;
    for (int kt = 0; kt < ktiles; kt++) {
        int k0 = kt * 64;
        const float* Kb = Kp + ((size_t)(b * Ss + k0)) * Dm + h * HDm;
        const float* Vb = V  + ((size_t)(b * Ss + k0)) * Dm + h * HDm;
        if (kt > 0) __syncthreads();
        for (int i = tid; i < 64 * 16; i += 128) {
            int r = i >> 4, c = (i & 15) * 4;
            float4 kv = *(const float4*)(Kb + (size_t)r * Dm + c);
            float4 vv = *(const float4*)(Vb + (size_t)r * Dm + c);
            uint4 tk, tv;
            tk.x = f2tf32(kv.x); tk.y = f2tf32(kv.y); tk.z = f2tf32(kv.z); tk.w = f2tf32(kv.w);
            tv.x = f2tf32(vv.x); tv.y = f2tf32(vv.y); tv.z = f2tf32(vv.z); tv.w = f2tf32(vv.w);
            *(uint4*)&Ks[r * ATS + c] = tk;
            *(uint4*)&Vs[r * ATS + c] = tv;
        }
        __syncthreads();

        float s[8][4];
        #pragma unroll
        for (int nc = 0; nc < 8; nc++)
            #pragma unroll
            for (int i = 0; i < 4; i++) s[nc][i] = 0.f;

        #pragma unroll
        for (int ks = 0; ks < 8; ks++) {
            int kb = ks * 8;
            uint32_t a0 = Qs[(r0 + grp) * ATS + kb + thr];
            uint32_t a1 = Qs[(r0 + grp + 8) * ATS + kb + thr];
            uint32_t a2 = Qs[(r0 + grp) * ATS + kb + thr + 4];
            uint32_t a3 = Qs[(r0 + grp + 8) * ATS + kb + thr + 4];
            #pragma unroll
            for (int nc = 0; nc < 8; nc++) {
                uint32_t b0 = Ks[(nc * 8 + grp) * ATS + kb + thr];
                uint32_t b1 = Ks[(nc * 8 + grp) * ATS + kb + thr + 4];
                asm("mma.sync.aligned.m16n8k8.row.col.f32.tf32.tf32.f32 "
                    "{%0,%1,%2,%3}, {%4,%5,%6,%7}, {%8,%9}, {%0,%1,%2,%3};"
                    : "+f"(s[nc][0]), "+f"(s[nc][1]), "+f"(s[nc][2]), "+f"(s[nc][3])
                    : "r"(a0), "r"(a1), "r"(a2), "r"(a3), "r"(b0), "r"(b1));
            }
        }

        #pragma unroll
        for (int nc = 0; nc < 8; nc++) {
            int ca = k0 + nc * 8 + 2 * thr;
            int cb = ca + 1;
            bool va = (amb[ca] != 0), vb = (amb[cb] != 0);
            if (!(ca <= qg0 && va)) s[nc][0] = -INFINITY;
            if (!(cb <= qg0 && vb)) s[nc][1] = -INFINITY;
            if (!(ca <= qg1 && va)) s[nc][2] = -INFINITY;
            if (!(cb <= qg1 && vb)) s[nc][3] = -INFINITY;
        }

        float t0 = -INFINITY, t1 = -INFINITY;
        #pragma unroll
        for (int nc = 0; nc < 8; nc++) {
            t0 = fmaxf(t0, fmaxf(s[nc][0], s[nc][1]));
            t1 = fmaxf(t1, fmaxf(s[nc][2], s[nc][3]));
        }
        t0 = fmaxf(t0, __shfl_xor_sync(0xffffffffu, t0, 1));
        t0 = fmaxf(t0, __shfl_xor_sync(0xffffffffu, t0, 2));
        t1 = fmaxf(t1, __shfl_xor_sync(0xffffffffu, t1, 1));
        t1 = fmaxf(t1, __shfl_xor_sync(0xffffffffu, t1, 2));

        float mn0 = fmaxf(m0, t0), mn1 = fmaxf(m1, t1);
        float al0 = (mn0 == -INFINITY) ? 1.f : __expf(m0 - mn0);
        float al1 = (mn1 == -INFINITY) ? 1.f : __expf(m1 - mn1);

        float ps0 = 0.f, ps1 = 0.f;
        #pragma unroll
        for (int nc = 0; nc < 8; nc++) {
            float p0 = (s[nc][0] == -INFINITY) ? 0.f : __expf(s[nc][0] - mn0);
            float p1 = (s[nc][1] == -INFINITY) ? 0.f : __expf(s[nc][1] - mn0);
            float p2 = (s[nc][2] == -INFINITY) ? 0.f : __expf(s[nc][2] - mn1);
            float p3 = (s[nc][3] == -INFINITY) ? 0.f : __expf(s[nc][3] - mn1);
            ps0 += p0 + p1;
            ps1 += p2 + p3;
            *(uint2*)&Ps[(r0 + grp) * ATS + nc * 8 + 2 * thr]     = make_uint2(f2tf32(p0), f2tf32(p1));
            *(uint2*)&Ps[(r0 + grp + 8) * ATS + nc * 8 + 2 * thr] = make_uint2(f2tf32(p2), f2tf32(p3));
        }
        ps0 += __shfl_xor_sync(0xffffffffu, ps0, 1);
        ps0 += __shfl_xor_sync(0xffffffffu, ps0, 2);
        ps1 += __shfl_xor_sync(0xffffffffu, ps1, 1);
        ps1 += __shfl_xor_sync(0xffffffffu, ps1, 2);

        l0 = l0 * al0 + ps0;
        l1 = l1 * al1 + ps1;
        m0 = mn0; m1 = mn1;

        #pragma unroll
        for (int nc = 0; nc < 8; nc++) {
            o[nc][0] *= al0; o[nc][1] *= al0;
            o[nc][2] *= al1; o[nc][3] *= al1;
        }
        __syncwarp();

        #pragma unroll
        for (int ks = 0; ks < 8; ks++) {
            int kb = ks * 8;
            uint32_t a0 = Ps[(r0 + grp) * ATS + kb + thr];
            uint32_t a1 = Ps[(r0 + grp + 8) * ATS + kb + thr];
            uint32_t a2 = Ps[(r0 + grp) * ATS + kb + thr + 4];
            uint32_t a3 = Ps[(r0 + grp + 8) * ATS + kb + thr + 4];
            #pragma unroll
            for (int nc = 0; nc < 8; nc++) {
                uint32_t b0 = Vs[(kb + thr) * ATS + nc * 8 + grp];
                uint32_t b1 = Vs[(kb + thr + 4) * ATS + nc * 8 + grp];
                asm("mma.sync.aligned.m16n8k8.row.col.f32.tf32.tf32.f32 "
                    "{%0,%1,%2,%3}, {%4,%5,%6,%7}, {%8,%9}, {%0,%1,%2,%3};"
                    : "+f"(o[nc][0]), "+f"(o[nc][1]), "+f"(o[nc][2]), "+f"(o[nc][3])
                    : "r"(a0), "r"(a1), "r"(a2), "r"(a3), "r"(b0), "r"(b1));
            }
        }
    }

    float rl0 = (l0 > 0.f) ? 1.f / l0 : 0.f;
    float rl1 = (l1 > 0.f) ? 1.f / l1 : 0.f;
    float* Ob = O + ((size_t)(b * Ss + q0)) * Dm + h * HDm;
    #pragma unroll
    for (int nc = 0; nc < 8; nc++) {
        int cc = nc * 8 + 2 * thr;
        // ctx feeds Wo GEMM as A -> store tf32(RNA)-rounded
        *(float2*)(Ob + (size_t)(r0 + grp) * Dm + cc)     = make_float2(rtf(o[nc][0] * rl0), rtf(o[nc][1] * rl0));
        *(float2*)(Ob + (size_t)(r0 + grp + 8) * Dm + cc) = make_float2(rtf(o[nc][2] * rl1), rtf(o[nc][3] * rl1));
    }
}

// ============================ launch ============================
extern "C" void kernel_launch(void* const* d_in, const int* in_sizes, int n_in,
                              void* d_out, int out_size) {
    const float* x     = (const float*)d_in[0];
    const int*   am    = (const int*)  d_in[1];
    const float* ln1_g = (const float*)d_in[2];
    const float* ln1_b = (const float*)d_in[3];
    const float* ln2_g = (const float*)d_in[4];
    const float* ln2_b = (const float*)d_in[5];
    const float* Wq = (const float*)d_in[6];
    const float* bq = (const float*)d_in[7];
    const float* Wk = (const float*)d_in[8];
    const float* bk = (const float*)d_in[9];
    const float* Wv = (const float*)d_in[10];
    const float* bv = (const float*)d_in[11];
    const float* Wo = (const float*)d_in[12];
    const float* bo = (const float*)d_in[13];
    const float* W1 = (const float*)d_in[14];
    const float* b1 = (const float*)d_in[15];
    const float* W2 = (const float*)d_in[16];
    const float* b2 = (const float*)d_in[17];
    float* out = (float*)d_out;

    float *h, *q, *k, *v, *ctx, *x1, *h2, *ff1, *wbuf;
    cudaGetSymbolAddress((void**)&h,    g_h);
    cudaGetSymbolAddress((void**)&q,    g_q);
    cudaGetSymbolAddress((void**)&k,    g_k);
    cudaGetSymbolAddress((void**)&v,    g_v);
    cudaGetSymbolAddress((void**)&ctx,  g_ctx);
    cudaGetSymbolAddress((void**)&x1,   g_x1);
    cudaGetSymbolAddress((void**)&h2,   g_h2);
    cudaGetSymbolAddress((void**)&ff1,  g_ff1);
    cudaGetSymbolAddress((void**)&wbuf, g_w);

    float* rWq = wbuf;
    float* rWk = rWq + Dm * Dm;
    float* rWv = rWk + Dm * Dm;
    float* rWo = rWv + Dm * Dm;
    float* rW1 = rWo + Dm * Dm;
    float* rW2 = rW1 + Dm * DFFm;

    // round weights to tf32 (RNA) once per launch
    {
        int nD = Dm * Dm / 4, nF = Dm * DFFm / 4;
        round_tf32_kernel<<<(nD + 255) / 256, 256>>>(Wq, rWq, nD);
        round_tf32_kernel<<<(nD + 255) / 256, 256>>>(Wk, rWk, nD);
        round_tf32_kernel<<<(nD + 255) / 256, 256>>>(Wv, rWv, nD);
        round_tf32_kernel<<<(nD + 255) / 256, 256>>>(Wo, rWo, nD);
        round_tf32_kernel<<<(nF + 255) / 256, 256>>>(W1, rW1, nF);
        round_tf32_kernel<<<(nF + 255) / 256, 256>>>(W2, rW2, nF);
    }

    cudaFuncSetAttribute(tf32gemm_kernel<false, false, false>, cudaFuncAttributeMaxDynamicSharedMemorySize, GEMM_SMEM);
    cudaFuncSetAttribute(tf32gemm_kernel<false, true,  false>, cudaFuncAttributeMaxDynamicSharedMemorySize, GEMM_SMEM);
    cudaFuncSetAttribute(tf32gemm_kernel<true,  false, true >, cudaFuncAttributeMaxDynamicSharedMemorySize, GEMM_SMEM);

    ln_kernel<<<NT, 256>>>(x, ln1_g, ln1_b, h);

    dim3 gD(Dm / 128, NT / 128);
    tf32gemm_kernel<false, false, false><<<gD, 256, GEMM_SMEM>>>(h, rWq, bq, nullptr, q, NT, Dm, Dm);
    tf32gemm_kernel<false, false, false><<<gD, 256, GEMM_SMEM>>>(h, rWk, bk, nullptr, k, NT, Dm, Dm);
    tf32gemm_kernel<false, false, false><<<gD, 256, GEMM_SMEM>>>(h, rWv, bv, nullptr, v, NT, Dm, Dm);

    const int ATTN_SMEM = 4 * 64 * ATS * 4;
    cudaFuncSetAttribute(attn_tc_kernel, cudaFuncAttributeMaxDynamicSharedMemorySize, ATTN_SMEM);
    attn_tc_kernel<<<dim3(Ss / 64, Hh, Bb), 128, ATTN_SMEM>>>(q, k, v, am, ctx);

    tf32gemm_kernel<false, true, false><<<gD, 256, GEMM_SMEM>>>(ctx, rWo, bo, x, x1, NT, Dm, Dm);

    ln_kernel<<<NT, 256>>>(x1, ln2_g, ln2_b, h2);

    tf32gemm_kernel<true, false, true><<<dim3(DFFm / 128, NT / 128), 256, GEMM_SMEM>>>(h2, rW1, b1, nullptr, ff1, NT, DFFm, Dm);
    tf32gemm_kernel<false, true, false><<<gD, 256, GEMM_SMEM>>>(ff1, rW2, b2, x1, out, NT, Dm, DFFm);
}